// round 1
// baseline (speedup 1.0000x reference)
#include <cuda_runtime.h>

// ---------------- problem constants ----------------
#define NNODES 100000
#define NEDGES 1600000
#define ETOT   (NEDGES + NNODES)   // edges + self loops
#define IN_DIM 8
#define HID    32
#define HEADS  4
#define F1     (HEADS * HID)       // 128
#define OUT_DIM 16

// ---------------- scratch (device globals; no allocation allowed) ----------------
__device__ __align__(16) float g_h1[NNODES * F1];        // 51.2 MB
__device__ __align__(16) float g_as1[NNODES * HEADS];
__device__ __align__(16) float g_ad1[NNODES * HEADS];
__device__ __align__(16) float g_agg1[NNODES * F1];      // 51.2 MB
__device__ __align__(16) float g_den1[NNODES * HEADS];
__device__ __align__(16) float g_h2[NNODES * OUT_DIM];
__device__ __align__(16) float g_as2[NNODES];
__device__ __align__(16) float g_ad2[NNODES];
__device__ __align__(16) float g_agg2[NNODES * OUT_DIM];
__device__ __align__(16) float g_den2[NNODES];
__device__ int g_is64;

// ---------------- helpers ----------------
__device__ __forceinline__ void red4(float* addr, float4 v) {
    asm volatile("red.global.add.v4.f32 [%0], {%1,%2,%3,%4};"
                 :: "l"(__cvta_generic_to_global(addr)),
                    "f"(v.x), "f"(v.y), "f"(v.z), "f"(v.w) : "memory");
}

__device__ __forceinline__ void load_edge(const void* __restrict__ ei, long long eid,
                                          int& src, int& dst) {
    if (eid < (long long)NEDGES) {
        if (g_is64) {
            const long long* p = (const long long*)ei;
            src = (int)p[eid];
            dst = (int)p[NEDGES + eid];
        } else {
            const int* p = (const int*)ei;
            src = p[eid];
            dst = p[NEDGES + eid];
        }
    } else {
        src = dst = (int)(eid - NEDGES);   // self loop
    }
}

// ---------------- K probe: detect int32 vs int64 edge_index ----------------
__global__ void k_probe(const void* __restrict__ ei) {
    if (threadIdx.x == 0) {
        const unsigned* w = (const unsigned*)ei;
        int is64 = 1;
        #pragma unroll
        for (int i = 0; i < 32; i++)
            if (w[2 * i + 1] != 0u) { is64 = 0; break; }
        g_is64 = is64;
    }
}

// ---------------- K0: h1 = x@W1, attention logits, zero accumulators ----------------
__global__ void k_node1(const float* __restrict__ x, const float* __restrict__ W1,
                        const float* __restrict__ as1, const float* __restrict__ ad1) {
    __shared__ float sW[IN_DIM * F1];
    __shared__ float sAs[F1], sAd[F1];
    int t = threadIdx.x;
    for (int i = t; i < IN_DIM * F1; i += blockDim.x) sW[i] = W1[i];
    if (t < F1) { sAs[t] = as1[t]; sAd[t] = ad1[t]; }
    __syncthreads();

    int gwarp = (blockIdx.x * blockDim.x + t) >> 5;
    int lane  = t & 31;
    if (gwarp >= NNODES) return;
    int n = gwarp;

    float xv[IN_DIM];
    #pragma unroll
    for (int i = 0; i < IN_DIM; i++) xv[i] = x[n * IN_DIM + i];

    const float4* sW4 = (const float4*)sW;
    float4 h = make_float4(0.f, 0.f, 0.f, 0.f);
    #pragma unroll
    for (int i = 0; i < IN_DIM; i++) {
        float4 w = sW4[i * 32 + lane];
        h.x = fmaf(xv[i], w.x, h.x);
        h.y = fmaf(xv[i], w.y, h.y);
        h.z = fmaf(xv[i], w.z, h.z);
        h.w = fmaf(xv[i], w.w, h.w);
    }
    ((float4*)g_h1)[n * 32 + lane]   = h;
    ((float4*)g_agg1)[n * 32 + lane] = make_float4(0.f, 0.f, 0.f, 0.f);

    float4 a = ((const float4*)sAs)[lane];
    float4 b = ((const float4*)sAd)[lane];
    float ps = h.x * a.x + h.y * a.y + h.z * a.z + h.w * a.w;
    float pd = h.x * b.x + h.y * b.y + h.z * b.z + h.w * b.w;
    #pragma unroll
    for (int s = 1; s < 8; s <<= 1) {
        ps += __shfl_xor_sync(0xffffffffu, ps, s);
        pd += __shfl_xor_sync(0xffffffffu, pd, s);
    }
    if ((lane & 7) == 0) {
        int head = lane >> 3;
        g_as1[n * HEADS + head] = ps;
        g_ad1[n * HEADS + head] = pd;
        g_den1[n * HEADS + head] = 0.f;
    }
}

// ---------------- K1: edge pass layer 1 (warp per edge) ----------------
__global__ void k_edge1(const void* __restrict__ ei) {
    long long gwarp = ((long long)blockIdx.x * blockDim.x + threadIdx.x) >> 5;
    int lane = threadIdx.x & 31;
    if (gwarp >= (long long)ETOT) return;

    int src, dst;
    load_edge(ei, gwarp, src, dst);

    int head = lane >> 3;
    float e = g_as1[src * HEADS + head] + g_ad1[dst * HEADS + head];
    e = fmaxf(e, 0.2f * e);               // leaky_relu(x, 0.2)
    float w = __expf(e);                  // softmax shift-invariance: no max pass

    if ((lane & 7) == 0) atomicAdd(&g_den1[dst * HEADS + head], w);

    float4 h = ((const float4*)g_h1)[src * 32 + lane];
    h.x *= w; h.y *= w; h.z *= w; h.w *= w;
    red4(&g_agg1[dst * F1 + lane * 4], h);
}

// ---------------- K2: normalize+elu layer1, h2 = hcat@W2, logits2, zero acc2 ----------------
__global__ void k_node2(const float* __restrict__ b1, const float* __restrict__ W2,
                        const float* __restrict__ as2, const float* __restrict__ ad2) {
    __shared__ float sW2T[OUT_DIM * F1];   // transposed: [o][c]
    __shared__ float sB1[F1];
    __shared__ float sAs[OUT_DIM], sAd[OUT_DIM];
    int t = threadIdx.x;
    for (int i = t; i < F1 * OUT_DIM; i += blockDim.x) {
        int c = i / OUT_DIM, o = i % OUT_DIM;
        sW2T[o * F1 + c] = W2[i];
    }
    if (t < F1) sB1[t] = b1[t];
    if (t < OUT_DIM) { sAs[t] = as2[t]; sAd[t] = ad2[t]; }
    __syncthreads();

    int gwarp = (blockIdx.x * blockDim.x + t) >> 5;
    int lane  = t & 31;
    if (gwarp >= NNODES) return;
    int n = gwarp;

    float4 acc = ((const float4*)g_agg1)[n * 32 + lane];
    float inv = 1.f / (g_den1[n * HEADS + (lane >> 3)] + 1e-16f);
    float4 b = ((const float4*)sB1)[lane];
    float hc[4];
    hc[0] = acc.x * inv + b.x;
    hc[1] = acc.y * inv + b.y;
    hc[2] = acc.z * inv + b.z;
    hc[3] = acc.w * inv + b.w;
    #pragma unroll
    for (int j = 0; j < 4; j++) hc[j] = hc[j] > 0.f ? hc[j] : expm1f(hc[j]);  // elu

    float p[OUT_DIM];
    #pragma unroll
    for (int o = 0; o < OUT_DIM; o++) {
        float4 w = *(const float4*)&sW2T[o * F1 + lane * 4];
        p[o] = hc[0] * w.x + hc[1] * w.y + hc[2] * w.z + hc[3] * w.w;
    }
    #pragma unroll
    for (int s = 1; s < 32; s <<= 1) {
        #pragma unroll
        for (int o = 0; o < OUT_DIM; o++) p[o] += __shfl_xor_sync(0xffffffffu, p[o], s);
    }
    if (lane == 0) {
        float4* o4 = (float4*)&g_h2[n * OUT_DIM];
        o4[0] = make_float4(p[0],  p[1],  p[2],  p[3]);
        o4[1] = make_float4(p[4],  p[5],  p[6],  p[7]);
        o4[2] = make_float4(p[8],  p[9],  p[10], p[11]);
        o4[3] = make_float4(p[12], p[13], p[14], p[15]);
        float s2 = 0.f, d2 = 0.f;
        #pragma unroll
        for (int o = 0; o < OUT_DIM; o++) { s2 += p[o] * sAs[o]; d2 += p[o] * sAd[o]; }
        g_as2[n] = s2;
        g_ad2[n] = d2;
        g_den2[n] = 0.f;
    }
    if (lane < 4) ((float4*)g_agg2)[n * 4 + lane] = make_float4(0.f, 0.f, 0.f, 0.f);
}

// ---------------- K3: edge pass layer 2 (4 threads per edge) ----------------
__global__ void k_edge2(const void* __restrict__ ei) {
    long long tid = (long long)blockIdx.x * blockDim.x + threadIdx.x;
    long long eid = tid >> 2;
    int sub = (int)(tid & 3);
    if (eid >= (long long)ETOT) return;

    int src, dst;
    load_edge(ei, eid, src, dst);

    float e = g_as2[src] + g_ad2[dst];
    e = fmaxf(e, 0.2f * e);
    float w = __expf(e);
    if (sub == 0) atomicAdd(&g_den2[dst], w);

    float4 h = ((const float4*)g_h2)[src * 4 + sub];
    h.x *= w; h.y *= w; h.z *= w; h.w *= w;
    red4(&g_agg2[dst * OUT_DIM + sub * 4], h);
}

// ---------------- K4: normalize+elu layer2, classifier head, write output ----------------
__global__ void k_final(const float* __restrict__ b2, const float* __restrict__ Wc1,
                        const float* __restrict__ bc1, const float* __restrict__ Wc2,
                        const float* __restrict__ bc2, float* __restrict__ out,
                        long long out_size) {
    int n = blockIdx.x * blockDim.x + threadIdx.x;
    if (n >= NNODES) return;

    float inv = 1.f / (g_den2[n] + 1e-16f);
    float emb[OUT_DIM];
    #pragma unroll
    for (int o = 0; o < OUT_DIM; o++) {
        float v = g_agg2[n * OUT_DIM + o] * inv + b2[o];
        emb[o] = v > 0.f ? v : expm1f(v);
    }

    if (out_size >= (long long)NNODES * OUT_DIM) {
        float4* o4 = (float4*)&out[(long long)n * OUT_DIM];
        o4[0] = make_float4(emb[0],  emb[1],  emb[2],  emb[3]);
        o4[1] = make_float4(emb[4],  emb[5],  emb[6],  emb[7]);
        o4[2] = make_float4(emb[8],  emb[9],  emb[10], emb[11]);
        o4[3] = make_float4(emb[12], emb[13], emb[14], emb[15]);
    }

    float tacc[8];
    #pragma unroll
    for (int k = 0; k < 8; k++) {
        float s = bc1[k];
        #pragma unroll
        for (int o = 0; o < OUT_DIM; o++) s = fmaf(emb[o], Wc1[o * 8 + k], s);
        tacc[k] = fmaxf(s, 0.f);
    }
    float z = bc2[0];
    #pragma unroll
    for (int k = 0; k < 8; k++) z = fmaf(tacc[k], Wc2[k], z);
    float risk = 1.f / (1.f + __expf(-z));

    if (out_size >= (long long)NNODES * (OUT_DIM + 1))
        out[(long long)NNODES * OUT_DIM + n] = risk;
    else if (out_size == (long long)NNODES)
        out[n] = risk;
}

// ---------------- launch ----------------
extern "C" void kernel_launch(void* const* d_in, const int* in_sizes, int n_in,
                              void* d_out, int out_size) {
    const float* x   = (const float*)d_in[0];
    const void*  ei  = d_in[1];
    const float* W1  = (const float*)d_in[2];
    const float* as1 = (const float*)d_in[3];
    const float* ad1 = (const float*)d_in[4];
    const float* b1  = (const float*)d_in[5];
    const float* W2  = (const float*)d_in[6];
    const float* as2 = (const float*)d_in[7];
    const float* ad2 = (const float*)d_in[8];
    const float* b2  = (const float*)d_in[9];
    const float* Wc1 = (const float*)d_in[10];
    const float* bc1 = (const float*)d_in[11];
    const float* Wc2 = (const float*)d_in[12];
    const float* bc2 = (const float*)d_in[13];

    k_probe<<<1, 32>>>(ei);

    int nodeBlocks = (NNODES * 32 + 255) / 256;                       // warp per node
    k_node1<<<nodeBlocks, 256>>>(x, W1, as1, ad1);

    long long e1Threads = (long long)ETOT * 32;                       // warp per edge
    int e1Blocks = (int)((e1Threads + 255) / 256);
    k_edge1<<<e1Blocks, 256>>>(ei);

    k_node2<<<nodeBlocks, 256>>>(b1, W2, as2, ad2);

    long long e2Threads = (long long)ETOT * 4;                        // 4 threads per edge
    int e2Blocks = (int)((e2Threads + 255) / 256);
    k_edge2<<<e2Blocks, 256>>>(ei);

    k_final<<<(NNODES + 255) / 256, 256>>>(b2, Wc1, bc1, Wc2, bc2,
                                           (float*)d_out, (long long)out_size);
}

// round 2
// speedup vs baseline: 1.0602x; 1.0602x over previous
#include <cuda_runtime.h>
#include <cuda_fp16.h>

// ---------------- problem constants ----------------
#define NNODES 100000
#define NEDGES 1600000
#define ETOT   (NEDGES + NNODES)   // edges + self loops
#define IN_DIM 8
#define HID    32
#define HEADS  4
#define F1     (HEADS * HID)       // 128
#define OUT_DIM 16

// ---------------- scratch (device globals; no allocation allowed) ----------------
__device__ __align__(16) __half g_h1h[NNODES * F1];      // 25.6 MB (fp16 gather operand)
__device__ __align__(16) float g_as1[NNODES * HEADS];
__device__ __align__(16) float g_ad1[NNODES * HEADS];
__device__ __align__(16) float g_agg1[NNODES * F1];      // 51.2 MB (fp32 accumulator)
__device__ __align__(16) float g_den1[NNODES * HEADS];
__device__ __align__(16) float g_h2[NNODES * OUT_DIM];
__device__ __align__(16) float g_as2[NNODES];
__device__ __align__(16) float g_ad2[NNODES];
__device__ __align__(16) float g_agg2[NNODES * OUT_DIM];
__device__ __align__(16) float g_den2[NNODES];
__device__ int g_is64;

// ---------------- helpers ----------------
__device__ __forceinline__ void red4(float* addr, float4 v) {
    asm volatile("red.global.add.v4.f32 [%0], {%1,%2,%3,%4};"
                 :: "l"(__cvta_generic_to_global(addr)),
                    "f"(v.x), "f"(v.y), "f"(v.z), "f"(v.w) : "memory");
}

// fast ELU: for x<0, exp(x) in (0,1] -> cancellation noise is ~1e-6 absolute, negligible
__device__ __forceinline__ float elu_fast(float v) {
    return v > 0.f ? v : (__expf(v) - 1.f);
}

__device__ __forceinline__ void load_edge(const void* __restrict__ ei, long long eid,
                                          int& src, int& dst) {
    if (eid < (long long)NEDGES) {
        if (g_is64) {
            const long long* p = (const long long*)ei;
            src = (int)p[eid];
            dst = (int)p[NEDGES + eid];
        } else {
            const int* p = (const int*)ei;
            src = p[eid];
            dst = p[NEDGES + eid];
        }
    } else {
        src = dst = (int)(eid - NEDGES);   // self loop
    }
}

// ---------------- K probe: detect int32 vs int64 edge_index ----------------
__global__ void k_probe(const void* __restrict__ ei) {
    if (threadIdx.x == 0) {
        const unsigned* w = (const unsigned*)ei;
        int is64 = 1;
        #pragma unroll
        for (int i = 0; i < 32; i++)
            if (w[2 * i + 1] != 0u) { is64 = 0; break; }
        g_is64 = is64;
    }
}

// ---------------- K0: h1 = x@W1, attention logits, zero accumulators ----------------
__global__ void __launch_bounds__(256) k_node1(
        const float* __restrict__ x, const float* __restrict__ W1,
        const float* __restrict__ as1, const float* __restrict__ ad1) {
    __shared__ float sW[IN_DIM * F1];
    __shared__ float sAs[F1], sAd[F1];
    int t = threadIdx.x;
    for (int i = t; i < IN_DIM * F1; i += blockDim.x) sW[i] = W1[i];
    if (t < F1) { sAs[t] = as1[t]; sAd[t] = ad1[t]; }
    __syncthreads();

    int gwarp = (blockIdx.x * blockDim.x + t) >> 5;
    int lane  = t & 31;
    if (gwarp >= NNODES) return;
    int n = gwarp;

    float xv[IN_DIM];
    #pragma unroll
    for (int i = 0; i < IN_DIM; i++) xv[i] = x[n * IN_DIM + i];

    const float4* sW4 = (const float4*)sW;
    float4 h = make_float4(0.f, 0.f, 0.f, 0.f);
    #pragma unroll
    for (int i = 0; i < IN_DIM; i++) {
        float4 w = sW4[i * 32 + lane];
        h.x = fmaf(xv[i], w.x, h.x);
        h.y = fmaf(xv[i], w.y, h.y);
        h.z = fmaf(xv[i], w.z, h.z);
        h.w = fmaf(xv[i], w.w, h.w);
    }

    // store h1 in fp16 (gather operand); logits stay fp32
    __half2 h01 = __floats2half2_rn(h.x, h.y);
    __half2 h23 = __floats2half2_rn(h.z, h.w);
    uint2 hv;
    hv.x = *(const unsigned*)&h01;
    hv.y = *(const unsigned*)&h23;
    ((uint2*)g_h1h)[n * 32 + lane] = hv;

    ((float4*)g_agg1)[n * 32 + lane] = make_float4(0.f, 0.f, 0.f, 0.f);

    float4 a = ((const float4*)sAs)[lane];
    float4 b = ((const float4*)sAd)[lane];
    float ps = h.x * a.x + h.y * a.y + h.z * a.z + h.w * a.w;
    float pd = h.x * b.x + h.y * b.y + h.z * b.z + h.w * b.w;
    #pragma unroll
    for (int s = 1; s < 8; s <<= 1) {
        ps += __shfl_xor_sync(0xffffffffu, ps, s);
        pd += __shfl_xor_sync(0xffffffffu, pd, s);
    }
    if ((lane & 7) == 0) {
        int head = lane >> 3;
        g_as1[n * HEADS + head] = ps;
        g_ad1[n * HEADS + head] = pd;
        g_den1[n * HEADS + head] = 0.f;
    }
}

// ---------------- K1: edge pass layer 1 (warp per edge) ----------------
__global__ void __launch_bounds__(256) k_edge1(const void* __restrict__ ei) {
    long long gwarp = ((long long)blockIdx.x * blockDim.x + threadIdx.x) >> 5;
    int lane = threadIdx.x & 31;
    if (gwarp >= (long long)ETOT) return;

    int src, dst;
    load_edge(ei, gwarp, src, dst);

    int head = lane >> 3;
    float e = g_as1[src * HEADS + head] + g_ad1[dst * HEADS + head];
    e = fmaxf(e, 0.2f * e);               // leaky_relu(x, 0.2)
    float w = __expf(e);                  // softmax shift-invariance: no max pass

    if ((lane & 7) == 0) atomicAdd(&g_den1[dst * HEADS + head], w);

    uint2 hv = ((const uint2*)g_h1h)[src * 32 + lane];
    float2 f01 = __half22float2(*(const __half2*)&hv.x);
    float2 f23 = __half22float2(*(const __half2*)&hv.y);
    float4 h = make_float4(f01.x * w, f01.y * w, f23.x * w, f23.y * w);
    red4(&g_agg1[dst * F1 + lane * 4], h);
}

// ---------------- K2: normalize+elu layer1, h2 = hcat@W2, logits2, zero acc2 ----------------
__global__ void __launch_bounds__(256) k_node2(
        const float* __restrict__ b1, const float* __restrict__ W2,
        const float* __restrict__ as2, const float* __restrict__ ad2) {
    __shared__ float sW2T[OUT_DIM * F1];   // transposed: [o][c]
    __shared__ float sB1[F1];
    __shared__ float sAs[OUT_DIM], sAd[OUT_DIM];
    int t = threadIdx.x;
    for (int i = t; i < F1 * OUT_DIM; i += blockDim.x) {
        int c = i / OUT_DIM, o = i % OUT_DIM;
        sW2T[o * F1 + c] = W2[i];
    }
    if (t < F1) sB1[t] = b1[t];
    if (t < OUT_DIM) { sAs[t] = as2[t]; sAd[t] = ad2[t]; }
    __syncthreads();

    int gwarp = (blockIdx.x * blockDim.x + t) >> 5;
    int lane  = t & 31;
    if (gwarp >= NNODES) return;
    int n = gwarp;

    float4 acc = ((const float4*)g_agg1)[n * 32 + lane];
    float inv = 1.f / (g_den1[n * HEADS + (lane >> 3)] + 1e-16f);
    float4 b = ((const float4*)sB1)[lane];
    float hc[4];
    hc[0] = elu_fast(acc.x * inv + b.x);
    hc[1] = elu_fast(acc.y * inv + b.y);
    hc[2] = elu_fast(acc.z * inv + b.z);
    hc[3] = elu_fast(acc.w * inv + b.w);

    float p[OUT_DIM];
    #pragma unroll
    for (int o = 0; o < OUT_DIM; o++) {
        float4 w = *(const float4*)&sW2T[o * F1 + lane * 4];
        p[o] = hc[0] * w.x + hc[1] * w.y + hc[2] * w.z + hc[3] * w.w;
    }
    #pragma unroll
    for (int s = 1; s < 32; s <<= 1) {
        #pragma unroll
        for (int o = 0; o < OUT_DIM; o++) p[o] += __shfl_xor_sync(0xffffffffu, p[o], s);
    }
    if (lane == 0) {
        float4* o4 = (float4*)&g_h2[n * OUT_DIM];
        o4[0] = make_float4(p[0],  p[1],  p[2],  p[3]);
        o4[1] = make_float4(p[4],  p[5],  p[6],  p[7]);
        o4[2] = make_float4(p[8],  p[9],  p[10], p[11]);
        o4[3] = make_float4(p[12], p[13], p[14], p[15]);
        float s2 = 0.f, d2 = 0.f;
        #pragma unroll
        for (int o = 0; o < OUT_DIM; o++) { s2 += p[o] * sAs[o]; d2 += p[o] * sAd[o]; }
        g_as2[n] = s2;
        g_ad2[n] = d2;
        g_den2[n] = 0.f;
    }
    if (lane < 4) ((float4*)g_agg2)[n * 4 + lane] = make_float4(0.f, 0.f, 0.f, 0.f);
}

// ---------------- K3: edge pass layer 2 (4 threads per edge) ----------------
__global__ void __launch_bounds__(256) k_edge2(const void* __restrict__ ei) {
    long long tid = (long long)blockIdx.x * blockDim.x + threadIdx.x;
    long long eid = tid >> 2;
    int sub = (int)(tid & 3);
    if (eid >= (long long)ETOT) return;

    int src, dst;
    load_edge(ei, eid, src, dst);

    float e = g_as2[src] + g_ad2[dst];
    e = fmaxf(e, 0.2f * e);
    float w = __expf(e);
    if (sub == 0) atomicAdd(&g_den2[dst], w);

    float4 h = ((const float4*)g_h2)[src * 4 + sub];
    h.x *= w; h.y *= w; h.z *= w; h.w *= w;
    red4(&g_agg2[dst * OUT_DIM + sub * 4], h);
}

// ---------------- K4: normalize+elu layer2, classifier head, write output ----------------
__global__ void __launch_bounds__(256) k_final(
        const float* __restrict__ b2, const float* __restrict__ Wc1,
        const float* __restrict__ bc1, const float* __restrict__ Wc2,
        const float* __restrict__ bc2, float* __restrict__ out,
        long long out_size) {
    int n = blockIdx.x * blockDim.x + threadIdx.x;
    if (n >= NNODES) return;

    float inv = 1.f / (g_den2[n] + 1e-16f);
    float emb[OUT_DIM];
    #pragma unroll
    for (int o = 0; o < OUT_DIM; o++) {
        float v = g_agg2[n * OUT_DIM + o] * inv + b2[o];
        emb[o] = elu_fast(v);
    }

    if (out_size >= (long long)NNODES * OUT_DIM) {
        float4* o4 = (float4*)&out[(long long)n * OUT_DIM];
        o4[0] = make_float4(emb[0],  emb[1],  emb[2],  emb[3]);
        o4[1] = make_float4(emb[4],  emb[5],  emb[6],  emb[7]);
        o4[2] = make_float4(emb[8],  emb[9],  emb[10], emb[11]);
        o4[3] = make_float4(emb[12], emb[13], emb[14], emb[15]);
    }

    float tacc[8];
    #pragma unroll
    for (int k = 0; k < 8; k++) {
        float s = bc1[k];
        #pragma unroll
        for (int o = 0; o < OUT_DIM; o++) s = fmaf(emb[o], Wc1[o * 8 + k], s);
        tacc[k] = fmaxf(s, 0.f);
    }
    float z = bc2[0];
    #pragma unroll
    for (int k = 0; k < 8; k++) z = fmaf(tacc[k], Wc2[k], z);
    float risk = 1.f / (1.f + __expf(-z));

    if (out_size >= (long long)NNODES * (OUT_DIM + 1))
        out[(long long)NNODES * OUT_DIM + n] = risk;
    else if (out_size == (long long)NNODES)
        out[n] = risk;
}

// ---------------- launch ----------------
extern "C" void kernel_launch(void* const* d_in, const int* in_sizes, int n_in,
                              void* d_out, int out_size) {
    const float* x   = (const float*)d_in[0];
    const void*  ei  = d_in[1];
    const float* W1  = (const float*)d_in[2];
    const float* as1 = (const float*)d_in[3];
    const float* ad1 = (const float*)d_in[4];
    const float* b1  = (const float*)d_in[5];
    const float* W2  = (const float*)d_in[6];
    const float* as2 = (const float*)d_in[7];
    const float* ad2 = (const float*)d_in[8];
    const float* b2  = (const float*)d_in[9];
    const float* Wc1 = (const float*)d_in[10];
    const float* bc1 = (const float*)d_in[11];
    const float* Wc2 = (const float*)d_in[12];
    const float* bc2 = (const float*)d_in[13];

    k_probe<<<1, 32>>>(ei);

    int nodeBlocks = (NNODES * 32 + 255) / 256;                       // warp per node
    k_node1<<<nodeBlocks, 256>>>(x, W1, as1, ad1);

    long long e1Threads = (long long)ETOT * 32;                       // warp per edge
    int e1Blocks = (int)((e1Threads + 255) / 256);
    k_edge1<<<e1Blocks, 256>>>(ei);

    k_node2<<<nodeBlocks, 256>>>(b1, W2, as2, ad2);

    long long e2Threads = (long long)ETOT * 4;                        // 4 threads per edge
    int e2Blocks = (int)((e2Threads + 255) / 256);
    k_edge2<<<e2Blocks, 256>>>(ei);

    k_final<<<(NNODES + 255) / 256, 256>>>(b2, Wc1, bc1, Wc2, bc2,
                                           (float*)d_out, (long long)out_size);
}

// round 3
// speedup vs baseline: 1.7151x; 1.6178x over previous
#include <cuda_runtime.h>
#include <cuda_fp16.h>

// ---------------- problem constants ----------------
#define NNODES 100000
#define NEDGES 1600000
#define ETOT   (NEDGES + NNODES)   // edges + self loops
#define IN_DIM 8
#define HID    32
#define HEADS  4
#define F1     (HEADS * HID)       // 128
#define OUT_DIM 16
#define SCAN_BS 1024
#define NB1 ((NNODES + SCAN_BS - 1) / SCAN_BS)   // 98

// ---------------- scratch (device globals; no allocation allowed) ----------------
__device__ __align__(16) __half g_h1h[NNODES * F1];      // 25.6 MB fp16 gather operand
__device__ __align__(16) float g_as1[NNODES * HEADS];
__device__ __align__(16) float g_ad1[NNODES * HEADS];
__device__ __align__(16) float g_h2[NNODES * OUT_DIM];
__device__ __align__(16) float g_as2[NNODES];
__device__ __align__(16) float g_ad2[NNODES];
// CSR build
__device__ int g_deg[NNODES];
__device__ int g_off[NNODES];          // exclusive scan within scan-block
__device__ int g_bsum[NB1];
__device__ int g_boff[NB1];
__device__ int g_start[NNODES + 1];
__device__ int g_cur[NNODES];
__device__ int g_srcs[ETOT];
__device__ int g_is64;

// ---------------- helpers ----------------
__device__ __forceinline__ float elu_fast(float v) {
    return v > 0.f ? v : (__expf(v) - 1.f);
}
__device__ __forceinline__ float lrelu_exp(float e) {
    e = fmaxf(e, 0.2f * e);
    return __expf(e);
}
__device__ __forceinline__ void load_edge(const void* __restrict__ ei, int eid,
                                          int& src, int& dst) {
    if (eid < NEDGES) {
        if (g_is64) {
            const long long* p = (const long long*)ei;
            src = (int)p[eid];
            dst = (int)p[NEDGES + eid];
        } else {
            const int* p = (const int*)ei;
            src = p[eid];
            dst = p[NEDGES + eid];
        }
    } else {
        src = dst = eid - NEDGES;   // self loop
    }
}

// ---------------- probe: int32 vs int64 edge_index ----------------
__global__ void k_probe(const void* __restrict__ ei) {
    if (threadIdx.x == 0) {
        const unsigned* w = (const unsigned*)ei;
        int is64 = 1;
        #pragma unroll
        for (int i = 0; i < 32; i++)
            if (w[2 * i + 1] != 0u) { is64 = 0; break; }
        g_is64 = is64;
    }
}

// ---------------- CSR build ----------------
__global__ void k_init_deg() {
    int n = blockIdx.x * blockDim.x + threadIdx.x;
    if (n < NNODES) g_deg[n] = 0;
}

__global__ void k_hist(const void* __restrict__ ei) {
    int e = blockIdx.x * blockDim.x + threadIdx.x;
    if (e >= ETOT) return;
    int src, dst;
    load_edge(ei, e, src, dst);
    atomicAdd(&g_deg[dst], 1);
}

__global__ void __launch_bounds__(SCAN_BS) k_scan_block() {
    __shared__ int s[SCAN_BS];
    int t = threadIdx.x;
    int g = blockIdx.x * SCAN_BS + t;
    int v = (g < NNODES) ? g_deg[g] : 0;
    s[t] = v;
    __syncthreads();
    #pragma unroll
    for (int off = 1; off < SCAN_BS; off <<= 1) {
        int add = (t >= off) ? s[t - off] : 0;
        __syncthreads();
        s[t] += add;
        __syncthreads();
    }
    if (g < NNODES) g_off[g] = s[t] - v;   // exclusive within block
    if (t == SCAN_BS - 1) g_bsum[blockIdx.x] = s[t];
}

__global__ void k_scan_tops() {
    if (threadIdx.x == 0) {
        int run = 0;
        for (int b = 0; b < NB1; b++) { g_boff[b] = run; run += g_bsum[b]; }
    }
}

__global__ void k_fillcur() {
    int n = blockIdx.x * blockDim.x + threadIdx.x;
    if (n < NNODES) {
        int s = g_off[n] + g_boff[n >> 10];
        g_start[n] = s;
        g_cur[n] = s;
    }
    if (n == 0) g_start[NNODES] = ETOT;
}

__global__ void k_scatter(const void* __restrict__ ei) {
    int e = blockIdx.x * blockDim.x + threadIdx.x;
    if (e >= ETOT) return;
    int src, dst;
    load_edge(ei, e, src, dst);
    int slot = atomicAdd(&g_cur[dst], 1);
    g_srcs[slot] = src;
}

// ---------------- K0: h1 = x@W1 (fp16 store), attention logits ----------------
__global__ void __launch_bounds__(256) k_node1(
        const float* __restrict__ x, const float* __restrict__ W1,
        const float* __restrict__ as1, const float* __restrict__ ad1) {
    __shared__ float sW[IN_DIM * F1];
    __shared__ float sAs[F1], sAd[F1];
    int t = threadIdx.x;
    for (int i = t; i < IN_DIM * F1; i += blockDim.x) sW[i] = W1[i];
    if (t < F1) { sAs[t] = as1[t]; sAd[t] = ad1[t]; }
    __syncthreads();

    int gwarp = (blockIdx.x * blockDim.x + t) >> 5;
    int lane  = t & 31;
    if (gwarp >= NNODES) return;
    int n = gwarp;

    float xv[IN_DIM];
    #pragma unroll
    for (int i = 0; i < IN_DIM; i++) xv[i] = x[n * IN_DIM + i];

    const float4* sW4 = (const float4*)sW;
    float4 h = make_float4(0.f, 0.f, 0.f, 0.f);
    #pragma unroll
    for (int i = 0; i < IN_DIM; i++) {
        float4 w = sW4[i * 32 + lane];
        h.x = fmaf(xv[i], w.x, h.x);
        h.y = fmaf(xv[i], w.y, h.y);
        h.z = fmaf(xv[i], w.z, h.z);
        h.w = fmaf(xv[i], w.w, h.w);
    }

    __half2 h01 = __floats2half2_rn(h.x, h.y);
    __half2 h23 = __floats2half2_rn(h.z, h.w);
    uint2 hv;
    hv.x = *(const unsigned*)&h01;
    hv.y = *(const unsigned*)&h23;
    ((uint2*)g_h1h)[n * 32 + lane] = hv;

    float4 a = ((const float4*)sAs)[lane];
    float4 b = ((const float4*)sAd)[lane];
    float ps = h.x * a.x + h.y * a.y + h.z * a.z + h.w * a.w;
    float pd = h.x * b.x + h.y * b.y + h.z * b.z + h.w * b.w;
    #pragma unroll
    for (int s = 1; s < 8; s <<= 1) {
        ps += __shfl_xor_sync(0xffffffffu, ps, s);
        pd += __shfl_xor_sync(0xffffffffu, pd, s);
    }
    if ((lane & 7) == 0) {
        int head = lane >> 3;
        g_as1[n * HEADS + head] = ps;
        g_ad1[n * HEADS + head] = pd;
    }
}

// ---------------- K1: fused layer-1 aggregate + ELU + W2 GEMM + layer-2 logits ----------------
// warp per dst node; gather-based (no atomics)
__global__ void __launch_bounds__(512) k_agg1(
        const float* __restrict__ b1, const float* __restrict__ W2,
        const float* __restrict__ as2v, const float* __restrict__ ad2v) {
    __shared__ float sW2T[OUT_DIM * F1];   // [o][c]
    __shared__ float sAs[OUT_DIM], sAd[OUT_DIM];
    int t = threadIdx.x;
    for (int i = t; i < F1 * OUT_DIM; i += 512) {
        int c = i / OUT_DIM, o = i % OUT_DIM;
        sW2T[o * F1 + c] = W2[i];
    }
    if (t < OUT_DIM) { sAs[t] = as2v[t]; sAd[t] = ad2v[t]; }
    __syncthreads();

    int n = (blockIdx.x * 512 + t) >> 5;
    int lane = t & 31;
    if (n >= NNODES) return;
    int head = lane >> 3;

    float ad_h = g_ad1[n * HEADS + head];
    int beg = g_start[n], end = g_start[n + 1];

    float4 acc = make_float4(0.f, 0.f, 0.f, 0.f);
    float den = 0.f;

    int i = beg;
    for (; i + 2 <= end; i += 2) {     // 2-way unroll for MLP
        int s0 = g_srcs[i], s1 = g_srcs[i + 1];
        float w0 = lrelu_exp(g_as1[s0 * HEADS + head] + ad_h);
        float w1 = lrelu_exp(g_as1[s1 * HEADS + head] + ad_h);
        uint2 hv0 = ((const uint2*)g_h1h)[s0 * 32 + lane];
        uint2 hv1 = ((const uint2*)g_h1h)[s1 * 32 + lane];
        float2 a01 = __half22float2(*(const __half2*)&hv0.x);
        float2 a23 = __half22float2(*(const __half2*)&hv0.y);
        float2 b01 = __half22float2(*(const __half2*)&hv1.x);
        float2 b23 = __half22float2(*(const __half2*)&hv1.y);
        acc.x = fmaf(a01.x, w0, fmaf(b01.x, w1, acc.x));
        acc.y = fmaf(a01.y, w0, fmaf(b01.y, w1, acc.y));
        acc.z = fmaf(a23.x, w0, fmaf(b23.x, w1, acc.z));
        acc.w = fmaf(a23.y, w0, fmaf(b23.y, w1, acc.w));
        den += w0 + w1;
    }
    if (i < end) {
        int s0 = g_srcs[i];
        float w0 = lrelu_exp(g_as1[s0 * HEADS + head] + ad_h);
        uint2 hv0 = ((const uint2*)g_h1h)[s0 * 32 + lane];
        float2 a01 = __half22float2(*(const __half2*)&hv0.x);
        float2 a23 = __half22float2(*(const __half2*)&hv0.y);
        acc.x = fmaf(a01.x, w0, acc.x);
        acc.y = fmaf(a01.y, w0, acc.y);
        acc.z = fmaf(a23.x, w0, acc.z);
        acc.w = fmaf(a23.y, w0, acc.w);
        den += w0;
    }

    float inv = 1.f / (den + 1e-16f);
    float4 bb = ((const float4*)b1)[lane];
    float hc0 = elu_fast(fmaf(acc.x, inv, bb.x));
    float hc1 = elu_fast(fmaf(acc.y, inv, bb.y));
    float hc2 = elu_fast(fmaf(acc.z, inv, bb.z));
    float hc3 = elu_fast(fmaf(acc.w, inv, bb.w));

    // GEMM partials: v[o] over this lane's 4 channels
    float v[OUT_DIM];
    #pragma unroll
    for (int o = 0; o < OUT_DIM; o++) {
        float4 w = *(const float4*)&sW2T[o * F1 + lane * 4];
        v[o] = hc0 * w.x + hc1 * w.y + hc2 * w.z + hc3 * w.w;
    }

    // butterfly fold: 16 values -> 1 per lane in 8+4+2+1 shuffles
    #pragma unroll
    for (int k = 0; k < 4; k++) {
        const int bit = 16 >> k;
        const int half = (16 >> k) >> 1;
        bool hi = (lane & bit) != 0;
        #pragma unroll
        for (int j = 0; j < half; j++) {
            float send = hi ? v[j] : v[j + half];
            float recv = __shfl_xor_sync(0xffffffffu, send, bit);
            v[j] = (hi ? v[j + half] : v[j]) + recv;
        }
    }
    v[0] += __shfl_xor_sync(0xffffffffu, v[0], 1);   // complete over bit0
    int o = (lane >> 1) & 15;
    float pv = v[0];

    if ((lane & 1) == 0) g_h2[n * OUT_DIM + o] = pv;

    // layer-2 logits: reduce p[o]*a[o] over one parity class (each o once)
    float ts = pv * sAs[o];
    float td = pv * sAd[o];
    #pragma unroll
    for (int bit = 2; bit <= 16; bit <<= 1) {
        ts += __shfl_xor_sync(0xffffffffu, ts, bit);
        td += __shfl_xor_sync(0xffffffffu, td, bit);
    }
    if (lane == 0) { g_as2[n] = ts; g_ad2[n] = td; }
}

// ---------------- K2: fused layer-2 aggregate + ELU + classifier + output ----------------
__global__ void __launch_bounds__(512) k_agg2(
        const float* __restrict__ b2, const float* __restrict__ Wc1,
        const float* __restrict__ bc1, const float* __restrict__ Wc2,
        const float* __restrict__ bc2, float* __restrict__ out,
        long long out_size) {
    int t = threadIdx.x;
    int n = (blockIdx.x * 512 + t) >> 5;
    int lane = t & 31;
    if (n >= NNODES) return;

    float ad_n = g_ad2[n];
    int beg = g_start[n], end = g_start[n + 1];

    float acc = 0.f, den = 0.f;
    int c = lane & 15;          // channel; lanes 16-31 duplicate channels 0-15
    int half = lane >> 4;       // 0 or 1: split edges between half-warps

    for (int i = beg + half; i < end; i += 2) {
        int src = g_srcs[i];
        float w = lrelu_exp(g_as2[src] + ad_n);
        float hv = g_h2[src * OUT_DIM + c];
        acc = fmaf(hv, w, acc);
        den += w;
    }
    // combine the two half-warp partials
    acc += __shfl_xor_sync(0xffffffffu, acc, 16);
    den += __shfl_xor_sync(0xffffffffu, den, 16);

    float inv = 1.f / (den + 1e-16f);
    float emb_l = elu_fast(fmaf(acc, inv, b2[c]));

    // broadcast emb to all lanes
    float emb[OUT_DIM];
    #pragma unroll
    for (int j = 0; j < OUT_DIM; j++)
        emb[j] = __shfl_sync(0xffffffffu, emb_l, j);

    if (out_size >= (long long)NNODES * OUT_DIM && lane < OUT_DIM)
        out[(long long)n * OUT_DIM + lane] = emb_l;

    // classifier (redundant in all lanes; cheap)
    float tacc[8];
    #pragma unroll
    for (int k = 0; k < 8; k++) {
        float s = bc1[k];
        #pragma unroll
        for (int j = 0; j < OUT_DIM; j++) s = fmaf(emb[j], Wc1[j * 8 + k], s);
        tacc[k] = fmaxf(s, 0.f);
    }
    float z = bc2[0];
    #pragma unroll
    for (int k = 0; k < 8; k++) z = fmaf(tacc[k], Wc2[k], z);
    float risk = 1.f / (1.f + __expf(-z));

    if (lane == 0) {
        if (out_size >= (long long)NNODES * (OUT_DIM + 1))
            out[(long long)NNODES * OUT_DIM + n] = risk;
        else if (out_size == (long long)NNODES)
            out[n] = risk;
    }
}

// ---------------- launch ----------------
extern "C" void kernel_launch(void* const* d_in, const int* in_sizes, int n_in,
                              void* d_out, int out_size) {
    const float* x   = (const float*)d_in[0];
    const void*  ei  = d_in[1];
    const float* W1  = (const float*)d_in[2];
    const float* as1 = (const float*)d_in[3];
    const float* ad1 = (const float*)d_in[4];
    const float* b1  = (const float*)d_in[5];
    const float* W2  = (const float*)d_in[6];
    const float* as2 = (const float*)d_in[7];
    const float* ad2 = (const float*)d_in[8];
    const float* b2  = (const float*)d_in[9];
    const float* Wc1 = (const float*)d_in[10];
    const float* bc1 = (const float*)d_in[11];
    const float* Wc2 = (const float*)d_in[12];
    const float* bc2 = (const float*)d_in[13];

    k_probe<<<1, 32>>>(ei);

    // CSR build
    k_init_deg<<<(NNODES + 255) / 256, 256>>>();
    k_hist<<<(ETOT + 255) / 256, 256>>>(ei);
    k_scan_block<<<NB1, SCAN_BS>>>();
    k_scan_tops<<<1, 32>>>();
    k_fillcur<<<(NNODES + 255) / 256, 256>>>();
    k_scatter<<<(ETOT + 255) / 256, 256>>>(ei);

    // node transform
    int nodeBlocks = (NNODES * 32 + 255) / 256;
    k_node1<<<nodeBlocks, 256>>>(x, W1, as1, ad1);

    // fused layers
    int aggBlocks = (NNODES * 32 + 511) / 512;
    k_agg1<<<aggBlocks, 512>>>(b1, W2, as2, ad2);
    k_agg2<<<aggBlocks, 512>>>(b2, Wc1, bc1, Wc2, bc2,
                               (float*)d_out, (long long)out_size);
}